// round 14
// baseline (speedup 1.0000x reference)
#include <cuda_runtime.h>
#include <math.h>

#define Bdim 128
#define Pdim 256
#define PIXdim 256
#define Ddim 512
#define Cdim 10

#define NSTATE (Bdim*Pdim*Ddim)   // 16,777,216
#define NATTN  (Bdim*Pdim*Pdim)   // 8,388,608
#define NROWS  (Bdim*Pdim)        // 32768

static __device__ float g_re0[NSTATE];
static __device__ float g_im0[NSTATE];
static __device__ float g_re1[NSTATE];
static __device__ float g_im1[NSTATE];
static __device__ float g_u_re[NSTATE];
static __device__ float g_u_im[NSTATE];
static __device__ float g_attn[NATTN];
static __device__ float g_pool_re[Bdim*Ddim];
static __device__ float g_pool_im[Bdim*Ddim];
static __device__ float g_cd[Ddim], g_sd[Ddim], g_cv[Ddim], g_sv[Ddim];
static __device__ double g_part_d[NROWS];
static __device__ double g_part_n[NROWS];
static __device__ int g_active;
static __device__ int g_cur;

// ---------------------------------------------------------------- prep
__global__ void k_prep(const float* __restrict__ qr, const float* __restrict__ kr,
                       const float* __restrict__ vr) {
    int d = threadIdx.x;
    if (d < Ddim) {
        float cq, sq, ck, sk, cv, sv;
        sincosf(qr[d], &sq, &cq);
        sincosf(kr[d], &sk, &ck);
        sincosf(vr[d], &sv, &cv);
        g_cd[d] = cq*ck + sq*sk;
        g_sd[d] = sq*ck - cq*sk;
        g_cv[d] = cv;
        g_sv[d] = sv;
    }
    if (d == 0) { g_active = 1; g_cur = 0; }
}

// ---------------------------------------------------------------- proj: state = tanh(x@Wp^T+bp) * e^{i phase}
__global__ void k_proj(const float* __restrict__ x, const float* __restrict__ Wp,
                       const float* __restrict__ bp) {
    __shared__ float As[16][68];
    __shared__ float Bs[16][68];
    const int tid = threadIdx.x;
    const int m0 = blockIdx.y * 64, n0 = blockIdx.x * 64;
    const int tm = (tid >> 4) * 4, tn = (tid & 15) * 4;
    const int lk = tid & 15, lr = tid >> 4;
    float acc[4][4] = {};
    for (int k0 = 0; k0 < PIXdim; k0 += 16) {
        #pragma unroll
        for (int i = 0; i < 4; i++) {
            As[lk][lr + 16*i] = x [(size_t)(m0 + lr + 16*i) * PIXdim + (k0 + lk)];
            Bs[lk][lr + 16*i] = Wp[(size_t)(n0 + lr + 16*i) * PIXdim + (k0 + lk)];
        }
        __syncthreads();
        #pragma unroll
        for (int kk = 0; kk < 16; kk++) {
            float a[4], b[4];
            #pragma unroll
            for (int i = 0; i < 4; i++) { a[i] = As[kk][tm+i]; b[i] = Bs[kk][tn+i]; }
            #pragma unroll
            for (int i = 0; i < 4; i++)
                #pragma unroll
                for (int j = 0; j < 4; j++)
                    acc[i][j] = fmaf(a[i], b[j], acc[i][j]);
        }
        __syncthreads();
    }
    const float PI = 3.14159265358979323846f;
    #pragma unroll
    for (int j = 0; j < 4; j++) {
        int n = n0 + tn + j;
        float freq = 1.0f / powf(10000.0f, (float)n / (float)Ddim);
        float bpv = bp[n];
        #pragma unroll
        for (int i = 0; i < 4; i++) {
            int m = m0 + tm + i;
            int p = m & (Pdim - 1);
            float t = tanhf(acc[i][j] + bpv);
            float ph = ((float)p * freq) * PI;
            float s, c;
            sincosf(ph, &s, &c);
            size_t idx = (size_t)m * Ddim + n;
            g_re0[idx] = t * c;
            g_im0[idx] = t * s;
        }
    }
}

// ---------------------------------------------------------------- QK^H * scale + FUSED softmax (R13 verbatim)
#define QKSM_FLOATS (64*260)
#define QKSM_BYTES  (QKSM_FLOATS*4)

__global__ void __launch_bounds__(256, 2) k_qk() {
    if (!g_active) return;
    extern __shared__ float sm[];
    float* Ar = sm;                    // [16][68]
    float* Ai = sm + 16*68;            // [16][68]
    float* Br = sm + 2*16*68;          // [16][260]
    float* Bi = sm + 2*16*68 + 16*260; // [16][260]
    const int tid = threadIdx.x;
    const int b = blockIdx.y;
    const int p0 = blockIdx.x * 64;
    const int tx = tid & 31, ty = tid >> 5;
    const int lk = tid & 15, lr = tid >> 4;
    const float* __restrict__ sre = (g_cur ? g_re1 : g_re0) + (size_t)b * Pdim * Ddim;
    const float* __restrict__ sim = (g_cur ? g_im1 : g_im0) + (size_t)b * Pdim * Ddim;
    float acc[8][8] = {};
    for (int k0 = 0; k0 < Ddim; k0 += 16) {
        int d = k0 + lk;
        float cd = g_cd[d], sd = g_sd[d];
        #pragma unroll
        for (int i = 0; i < 4; i++) {
            int pr = p0 + lr + 16*i;
            float re = sre[(size_t)pr * Ddim + d];
            float im = sim[(size_t)pr * Ddim + d];
            Ar[lk*68 + lr + 16*i] = re * cd - im * sd;
            Ai[lk*68 + lr + 16*i] = re * sd + im * cd;
        }
        #pragma unroll
        for (int i = 0; i < 16; i++) {
            int qq = lr + 16*i;
            Br[lk*260 + qq] = sre[(size_t)qq * Ddim + d];
            Bi[lk*260 + qq] = sim[(size_t)qq * Ddim + d];
        }
        __syncthreads();
        #pragma unroll
        for (int kk = 0; kk < 16; kk++) {
            float ar[8], ai2[8], br[8], bi2[8];
            #pragma unroll
            for (int i = 0; i < 8; i++) {
                ar[i]  = Ar[kk*68 + ty*8 + i];
                ai2[i] = Ai[kk*68 + ty*8 + i];
            }
            #pragma unroll
            for (int j = 0; j < 8; j++) {
                br[j]  = Br[kk*260 + tx*8 + j];
                bi2[j] = Bi[kk*260 + tx*8 + j];
            }
            #pragma unroll
            for (int i = 0; i < 8; i++)
                #pragma unroll
                for (int j = 0; j < 8; j++) {
                    acc[i][j] = fmaf(ar[i],  br[j],  acc[i][j]);
                    acc[i][j] = fmaf(ai2[i], bi2[j], acc[i][j]);
                }
        }
        __syncthreads();
    }
    const float SCALE = 0.3535533905932738f;  // 8/sqrt(512)
    float* att = sm;                   // [64][260]
    #pragma unroll
    for (int i = 0; i < 8; i++)
        #pragma unroll
        for (int j = 0; j < 8; j++)
            att[(ty*8 + i)*260 + tx*8 + j] = acc[i][j] * SCALE;
    __syncthreads();
    const int lane = tid & 31, wrp = tid >> 5;
    float* out = g_attn + (size_t)b * Pdim * Pdim;
    #pragma unroll 1
    for (int pass = 0; pass < 8; pass++) {
        int r = pass * 8 + wrp;
        float v[8];
        #pragma unroll
        for (int c = 0; c < 8; c++) v[c] = att[r*260 + lane + 32*c];
        float w[8];
        #pragma unroll
        for (int c = 0; c < 8; c++) w[c] = v[c];
        #pragma unroll
        for (int c = 0; c < 4; c++) w[c] = fmaxf(w[c], w[c+4]);
        w[0] = fmaxf(w[0], w[2]); w[1] = fmaxf(w[1], w[3]);
        float m = fmaxf(w[0], w[1]);
        #pragma unroll
        for (int s = 16; s > 0; s >>= 1)
            m = fmaxf(m, __shfl_down_sync(0xffffffffu, m, s));
        float mx = __shfl_sync(0xffffffffu, m, 0);
        float e[8];
        #pragma unroll
        for (int c = 0; c < 8; c++) e[c] = expf(v[c] - mx);
        float t[8];
        #pragma unroll
        for (int c = 0; c < 8; c++) t[c] = e[c];
        #pragma unroll
        for (int c = 0; c < 4; c++) t[c] += t[c+4];
        t[0] += t[2]; t[1] += t[3];
        float s0 = t[0] + t[1];
        #pragma unroll
        for (int s = 16; s > 0; s >>= 1)
            s0 += __shfl_down_sync(0xffffffffu, s0, s);
        float sum = __shfl_sync(0xffffffffu, s0, 0);
        #pragma unroll
        for (int c = 0; c < 8; c++)
            out[(size_t)(p0 + r) * Pdim + lane + 32*c] = e[c] / sum;
    }
}

// ---------------------------------------------------------------- u = prev + e^{iv} * (attn @ state)  (8x4 retile, same chains)
__global__ void __launch_bounds__(256, 2) k_av() {
    if (!g_active) return;
    __shared__ float As[16][132];
    __shared__ float Br[16][68], Bi[16][68];
    const int tid = threadIdx.x;
    const int b = blockIdx.z;
    const int p0 = blockIdx.y * 128, n0 = blockIdx.x * 64;
    const int tm = (tid >> 4) * 8, tn = (tid & 15) * 4;
    const int lk = tid & 15, lr = tid >> 4;
    const int ln = tid & 63, lkb = tid >> 6;
    const float* __restrict__ sre = (g_cur ? g_re1 : g_re0) + (size_t)b * Pdim * Ddim;
    const float* __restrict__ sim = (g_cur ? g_im1 : g_im0) + (size_t)b * Pdim * Ddim;
    const float* __restrict__ at  = g_attn + (size_t)b * Pdim * Pdim;
    float ar[8][4] = {}, ai[8][4] = {};
    for (int k0 = 0; k0 < Pdim; k0 += 16) {
        #pragma unroll
        for (int i = 0; i < 8; i++)
            As[lk][lr + 16*i] = at[(size_t)(p0 + lr + 16*i) * Pdim + (k0 + lk)];
        #pragma unroll
        for (int i = 0; i < 4; i++) {
            int kq = k0 + lkb * 4 + i;
            Br[lkb*4 + i][ln] = sre[(size_t)kq * Ddim + n0 + ln];
            Bi[lkb*4 + i][ln] = sim[(size_t)kq * Ddim + n0 + ln];
        }
        __syncthreads();
        #pragma unroll
        for (int kk = 0; kk < 16; kk++) {
            float a[8];
            #pragma unroll
            for (int i = 0; i < 8; i++) a[i] = As[kk][tm+i];
            float4 br4 = *reinterpret_cast<const float4*>(&Br[kk][tn]);
            float4 bi4 = *reinterpret_cast<const float4*>(&Bi[kk][tn]);
            float br[4] = {br4.x, br4.y, br4.z, br4.w};
            float bi[4] = {bi4.x, bi4.y, bi4.z, bi4.w};
            #pragma unroll
            for (int i = 0; i < 8; i++)
                #pragma unroll
                for (int j = 0; j < 4; j++) {
                    ar[i][j] = fmaf(a[i], br[j], ar[i][j]);
                    ai[i][j] = fmaf(a[i], bi[j], ai[i][j]);
                }
        }
        __syncthreads();
    }
    #pragma unroll
    for (int j = 0; j < 4; j++) {
        int d = n0 + tn + j;
        float cv = g_cv[d], sv = g_sv[d];
        #pragma unroll
        for (int i = 0; i < 8; i++) {
            int p = p0 + tm + i;
            size_t idx = (size_t)b * Pdim * Ddim + (size_t)p * Ddim + d;
            float tr = ar[i][j], ti = ai[i][j];
            g_u_re[idx] = sre[(size_t)p * Ddim + d] + cv * tr - sv * ti;
            g_u_im[idx] = sim[(size_t)p * Ddim + d] + sv * tr + cv * ti;
        }
    }
}

// ---------------------------------------------------------------- new = u @ (ffr + i*ffi)  (8x4 retile, same chains)
__global__ void __launch_bounds__(256, 2) k_ff(const float* __restrict__ ffr,
                                               const float* __restrict__ ffi) {
    if (!g_active) return;
    __shared__ float Aur[16][132], Aui[16][132];
    __shared__ float Bfr[16][68], Bfi[16][68];
    const int tid = threadIdx.x;
    const int m0 = blockIdx.y * 128, n0 = blockIdx.x * 64;
    const int tm = (tid >> 4) * 8, tn = (tid & 15) * 4;
    const int lk = tid & 15, lr = tid >> 4;
    const int ln = tid & 63, lkb = tid >> 6;
    float* __restrict__ nre = g_cur ? g_re0 : g_re1;
    float* __restrict__ nim = g_cur ? g_im0 : g_im1;
    float cr[8][4] = {}, ci[8][4] = {};
    for (int k0 = 0; k0 < Ddim; k0 += 16) {
        #pragma unroll
        for (int i = 0; i < 8; i++) {
            size_t ga = (size_t)(m0 + lr + 16*i) * Ddim + (k0 + lk);
            Aur[lk][lr + 16*i] = g_u_re[ga];
            Aui[lk][lr + 16*i] = g_u_im[ga];
        }
        #pragma unroll
        for (int i = 0; i < 4; i++) {
            int kd = k0 + lkb * 4 + i;
            Bfr[lkb*4 + i][ln] = ffr[(size_t)kd * Ddim + n0 + ln];
            Bfi[lkb*4 + i][ln] = ffi[(size_t)kd * Ddim + n0 + ln];
        }
        __syncthreads();
        #pragma unroll
        for (int kk = 0; kk < 16; kk++) {
            float ur[8], ui[8];
            #pragma unroll
            for (int i = 0; i < 8; i++) {
                ur[i] = Aur[kk][tm+i];
                ui[i] = Aui[kk][tm+i];
            }
            float4 fr4 = *reinterpret_cast<const float4*>(&Bfr[kk][tn]);
            float4 fi4 = *reinterpret_cast<const float4*>(&Bfi[kk][tn]);
            float fr[4] = {fr4.x, fr4.y, fr4.z, fr4.w};
            float fi[4] = {fi4.x, fi4.y, fi4.z, fi4.w};
            #pragma unroll
            for (int i = 0; i < 8; i++)
                #pragma unroll
                for (int j = 0; j < 4; j++) {
                    cr[i][j] = fmaf(ur[i],  fr[j], cr[i][j]);
                    cr[i][j] = fmaf(-ui[i], fi[j], cr[i][j]);
                    ci[i][j] = fmaf(ur[i],  fi[j], ci[i][j]);
                    ci[i][j] = fmaf(ui[i],  fr[j], ci[i][j]);
                }
        }
        __syncthreads();
    }
    #pragma unroll
    for (int i = 0; i < 8; i++)
        #pragma unroll
        for (int j = 0; j < 4; j++) {
            size_t idx = (size_t)(m0 + tm + i) * Ddim + (n0 + tn + j);
            nre[idx] = cr[i][j];
            nim[idx] = ci[i][j];
        }
}

// ---------------------------------------------------------------- complex_norm (R1 expressions) + fused diff partials
__global__ void k_norm() {
    if (!g_active) return;
    float* nre = g_cur ? g_re0 : g_re1;
    float* nim = g_cur ? g_im0 : g_im1;
    const float* pre = g_cur ? g_re1 : g_re0;
    const float* pim = g_cur ? g_im1 : g_im0;
    const int row = blockIdx.x;
    const int tid = threadIdx.x;
    const size_t base = (size_t)row * Ddim;
    float r0 = nre[base + tid],       i0 = nim[base + tid];
    float r1 = nre[base + tid + 256], i1 = nim[base + tid + 256];
    float m0 = sqrtf(r0*r0 + i0*i0);
    float m1 = sqrtf(r1*r1 + i1*i1);
    __shared__ float s_sum[256], s_sq[256];
    s_sum[tid] = m0 + m1;
    s_sq[tid]  = m0*m0 + m1*m1;
    __syncthreads();
    for (int s = 128; s > 0; s >>= 1) {
        if (tid < s) { s_sum[tid] += s_sum[tid+s]; s_sq[tid] += s_sq[tid+s]; }
        __syncthreads();
    }
    float mean = s_sum[0] * (1.0f / 512.0f);
    float var  = (s_sq[0] - 512.0f * mean * mean) * (1.0f / 511.0f);
    var = fmaxf(var, 0.0f);
    float inv = 1.0f / (sqrtf(var) + 1e-5f);
    float sc0 = tanhf((m0 - mean) * inv) / (m0 + 1e-5f);
    float sc1 = tanhf((m1 - mean) * inv) / (m1 + 1e-5f);
    float nr0 = r0 * sc0, ni0 = i0 * sc0;
    float nr1 = r1 * sc1, ni1 = i1 * sc1;
    nre[base + tid]       = nr0;
    nim[base + tid]       = ni0;
    nre[base + tid + 256] = nr1;
    nim[base + tid + 256] = ni1;
    __shared__ double sd[256], sn[256];
    float pr0 = pre[base + tid],       qi0 = pim[base + tid];
    float pr1 = pre[base + tid + 256], qi1 = pim[base + tid + 256];
    float dr0 = nr0 - pr0, di0 = ni0 - qi0;
    float dr1 = nr1 - pr1, di1 = ni1 - qi1;
    sd[tid] = (double)dr0*dr0 + (double)di0*di0 + (double)dr1*dr1 + (double)di1*di1;
    sn[tid] = (double)nr0*nr0 + (double)ni0*ni0 + (double)nr1*nr1 + (double)ni1*ni1;
    __syncthreads();
    for (int s = 128; s > 0; s >>= 1) {
        if (tid < s) { sd[tid] += sd[tid+s]; sn[tid] += sn[tid+s]; }
        __syncthreads();
    }
    if (tid == 0) { g_part_d[row] = sd[0]; g_part_n[row] = sn[0]; }
}

// ---------------------------------------------------------------- flag: reduce partials, swap buffers
__global__ void k_flag() {
    if (!g_active) return;
    const int tid = threadIdx.x;
    double ld = 0.0, lnn = 0.0;
    for (int i = tid; i < NROWS; i += 1024) { ld += g_part_d[i]; lnn += g_part_n[i]; }
    __shared__ double sd[1024], sn[1024];
    sd[tid] = ld; sn[tid] = lnn;
    __syncthreads();
    for (int s = 512; s > 0; s >>= 1) {
        if (tid < s) { sd[tid] += sd[tid+s]; sn[tid] += sn[tid+s]; }
        __syncthreads();
    }
    if (tid == 0) {
        float diff = (float)(sqrt(sd[0]) / (sqrt(sn[0]) + 1e-8));
        g_cur ^= 1;                          // commit = buffer swap (active known true here)
        if (diff < 1e-3f) g_active = 0;
    }
}

// ---------------------------------------------------------------- mean pool over P
__global__ void k_pool() {
    const float* sre = g_cur ? g_re1 : g_re0;
    const float* sim = g_cur ? g_im1 : g_im0;
    const int idx = blockIdx.x * 256 + threadIdx.x;   // b*D + d
    const int b = idx >> 9, d = idx & (Ddim - 1);
    const size_t base = (size_t)b * Pdim * Ddim + d;
    float accr = 0.0f, acci = 0.0f;
    #pragma unroll 8
    for (int p = 0; p < Pdim; p++) {
        accr += sre[base + (size_t)p * Ddim];
        acci += sim[base + (size_t)p * Ddim];
    }
    g_pool_re[idx] = accr * (1.0f / 256.0f);
    g_pool_im[idx] = acci * (1.0f / 256.0f);
}

// ---------------------------------------------------------------- logits
__global__ void k_logits(float* __restrict__ out, const float* __restrict__ Wr,
                         const float* __restrict__ br, const float* __restrict__ Wi,
                         const float* __restrict__ bi) {
    const int b = blockIdx.x, tid = threadIdx.x;
    float pr0 = g_pool_re[b * Ddim + tid],       pi0 = g_pool_im[b * Ddim + tid];
    float pr1 = g_pool_re[b * Ddim + tid + 256], pi1 = g_pool_im[b * Ddim + tid + 256];
    __shared__ float red[256];
    for (int c = 0; c < Cdim; c++) {
        float v = pr0 * Wr[c * Ddim + tid] + pr1 * Wr[c * Ddim + tid + 256]
                + pi0 * Wi[c * Ddim + tid] + pi1 * Wi[c * Ddim + tid + 256];
        red[tid] = v;
        __syncthreads();
        for (int s = 128; s > 0; s >>= 1) {
            if (tid < s) red[tid] += red[tid+s];
            __syncthreads();
        }
        if (tid == 0) out[b * Cdim + c] = red[0] + br[c] + bi[c];
        __syncthreads();
    }
}

// ---------------------------------------------------------------- launch
extern "C" void kernel_launch(void* const* d_in, const int* in_sizes, int n_in,
                              void* d_out, int out_size) {
    const float* x   = (const float*)d_in[0];
    const float* Wp  = (const float*)d_in[1];
    const float* bp  = (const float*)d_in[2];
    const float* qr  = (const float*)d_in[3];
    const float* kr  = (const float*)d_in[4];
    const float* vr  = (const float*)d_in[5];
    const float* ffr = (const float*)d_in[6];
    const float* ffi = (const float*)d_in[7];
    const float* Wr  = (const float*)d_in[8];
    const float* br  = (const float*)d_in[9];
    const float* Wi  = (const float*)d_in[10];
    const float* bi  = (const float*)d_in[11];
    float* out = (float*)d_out;

    cudaFuncSetAttribute(k_qk, cudaFuncAttributeMaxDynamicSharedMemorySize, QKSM_BYTES);

    k_prep<<<1, 512>>>(qr, kr, vr);
    k_proj<<<dim3(Ddim/64, (Bdim*Pdim)/64), 256>>>(x, Wp, bp);
    for (int step = 0; step < 4; step++) {
        k_qk<<<dim3(Pdim/64, Bdim), 256, QKSM_BYTES>>>();
        k_av<<<dim3(Ddim/64, Pdim/128, Bdim), 256>>>();
        k_ff<<<dim3(Ddim/64, (Bdim*Pdim)/128), 256>>>(ffr, ffi);
        k_norm<<<Bdim*Pdim, 256>>>();
        k_flag<<<1, 1024>>>();
    }
    k_pool<<<(Bdim*Ddim)/256, 256>>>();
    k_logits<<<Bdim, 256>>>(out, Wr, br, Wi, bi);
}

// round 15
// speedup vs baseline: 1.0615x; 1.0615x over previous
#include <cuda_runtime.h>
#include <math.h>

#define Bdim 128
#define Pdim 256
#define PIXdim 256
#define Ddim 512
#define Cdim 10

#define NSTATE (Bdim*Pdim*Ddim)   // 16,777,216
#define NATTN  (Bdim*Pdim*Pdim)   // 8,388,608
#define NROWS  (Bdim*Pdim)        // 32768

static __device__ float g_re0[NSTATE];
static __device__ float g_im0[NSTATE];
static __device__ float g_re1[NSTATE];
static __device__ float g_im1[NSTATE];
static __device__ float g_u_re[NSTATE];
static __device__ float g_u_im[NSTATE];
static __device__ float g_attn[NATTN];
static __device__ float g_pool_re[Bdim*Ddim];
static __device__ float g_pool_im[Bdim*Ddim];
static __device__ float g_cd[Ddim], g_sd[Ddim], g_cv[Ddim], g_sv[Ddim];
static __device__ double g_part_d[NROWS];
static __device__ double g_part_n[NROWS];
static __device__ int g_active;
static __device__ int g_cur;

// ---------------------------------------------------------------- prep
__global__ void k_prep(const float* __restrict__ qr, const float* __restrict__ kr,
                       const float* __restrict__ vr) {
    int d = threadIdx.x;
    if (d < Ddim) {
        float cq, sq, ck, sk, cv, sv;
        sincosf(qr[d], &sq, &cq);
        sincosf(kr[d], &sk, &ck);
        sincosf(vr[d], &sv, &cv);
        g_cd[d] = cq*ck + sq*sk;
        g_sd[d] = sq*ck - cq*sk;
        g_cv[d] = cv;
        g_sv[d] = sv;
    }
    if (d == 0) { g_active = 1; g_cur = 0; }
}

// ---------------------------------------------------------------- proj: state = tanh(x@Wp^T+bp) * e^{i phase}
__global__ void k_proj(const float* __restrict__ x, const float* __restrict__ Wp,
                       const float* __restrict__ bp) {
    __shared__ float As[16][68];
    __shared__ float Bs[16][68];
    const int tid = threadIdx.x;
    const int m0 = blockIdx.y * 64, n0 = blockIdx.x * 64;
    const int tm = (tid >> 4) * 4, tn = (tid & 15) * 4;
    const int lk = tid & 15, lr = tid >> 4;
    float acc[4][4] = {};
    for (int k0 = 0; k0 < PIXdim; k0 += 16) {
        #pragma unroll
        for (int i = 0; i < 4; i++) {
            As[lk][lr + 16*i] = x [(size_t)(m0 + lr + 16*i) * PIXdim + (k0 + lk)];
            Bs[lk][lr + 16*i] = Wp[(size_t)(n0 + lr + 16*i) * PIXdim + (k0 + lk)];
        }
        __syncthreads();
        #pragma unroll
        for (int kk = 0; kk < 16; kk++) {
            float a[4], b[4];
            #pragma unroll
            for (int i = 0; i < 4; i++) { a[i] = As[kk][tm+i]; b[i] = Bs[kk][tn+i]; }
            #pragma unroll
            for (int i = 0; i < 4; i++)
                #pragma unroll
                for (int j = 0; j < 4; j++)
                    acc[i][j] = fmaf(a[i], b[j], acc[i][j]);
        }
        __syncthreads();
    }
    const float PI = 3.14159265358979323846f;
    #pragma unroll
    for (int j = 0; j < 4; j++) {
        int n = n0 + tn + j;
        float freq = 1.0f / powf(10000.0f, (float)n / (float)Ddim);
        float bpv = bp[n];
        #pragma unroll
        for (int i = 0; i < 4; i++) {
            int m = m0 + tm + i;
            int p = m & (Pdim - 1);
            float t = tanhf(acc[i][j] + bpv);
            float ph = ((float)p * freq) * PI;
            float s, c;
            sincosf(ph, &s, &c);
            size_t idx = (size_t)m * Ddim + n;
            g_re0[idx] = t * c;
            g_im0[idx] = t * s;
        }
    }
}

// ---------------------------------------------------------------- QK^H * scale + FUSED softmax (R13 verbatim)
#define QKSM_FLOATS (64*260)
#define QKSM_BYTES  (QKSM_FLOATS*4)

__global__ void __launch_bounds__(256, 2) k_qk() {
    if (!g_active) return;
    extern __shared__ float sm[];
    float* Ar = sm;                    // [16][68]
    float* Ai = sm + 16*68;            // [16][68]
    float* Br = sm + 2*16*68;          // [16][260]
    float* Bi = sm + 2*16*68 + 16*260; // [16][260]
    const int tid = threadIdx.x;
    const int b = blockIdx.y;
    const int p0 = blockIdx.x * 64;
    const int tx = tid & 31, ty = tid >> 5;
    const int lk = tid & 15, lr = tid >> 4;
    const float* __restrict__ sre = (g_cur ? g_re1 : g_re0) + (size_t)b * Pdim * Ddim;
    const float* __restrict__ sim = (g_cur ? g_im1 : g_im0) + (size_t)b * Pdim * Ddim;
    float acc[8][8] = {};
    for (int k0 = 0; k0 < Ddim; k0 += 16) {
        int d = k0 + lk;
        float cd = g_cd[d], sd = g_sd[d];
        #pragma unroll
        for (int i = 0; i < 4; i++) {
            int pr = p0 + lr + 16*i;
            float re = sre[(size_t)pr * Ddim + d];
            float im = sim[(size_t)pr * Ddim + d];
            Ar[lk*68 + lr + 16*i] = re * cd - im * sd;
            Ai[lk*68 + lr + 16*i] = re * sd + im * cd;
        }
        #pragma unroll
        for (int i = 0; i < 16; i++) {
            int qq = lr + 16*i;
            Br[lk*260 + qq] = sre[(size_t)qq * Ddim + d];
            Bi[lk*260 + qq] = sim[(size_t)qq * Ddim + d];
        }
        __syncthreads();
        #pragma unroll
        for (int kk = 0; kk < 16; kk++) {
            float ar[8], ai2[8], br[8], bi2[8];
            #pragma unroll
            for (int i = 0; i < 8; i++) {
                ar[i]  = Ar[kk*68 + ty*8 + i];
                ai2[i] = Ai[kk*68 + ty*8 + i];
            }
            #pragma unroll
            for (int j = 0; j < 8; j++) {
                br[j]  = Br[kk*260 + tx*8 + j];
                bi2[j] = Bi[kk*260 + tx*8 + j];
            }
            #pragma unroll
            for (int i = 0; i < 8; i++)
                #pragma unroll
                for (int j = 0; j < 8; j++) {
                    acc[i][j] = fmaf(ar[i],  br[j],  acc[i][j]);
                    acc[i][j] = fmaf(ai2[i], bi2[j], acc[i][j]);
                }
        }
        __syncthreads();
    }
    const float SCALE = 0.3535533905932738f;  // 8/sqrt(512)
    float* att = sm;                   // [64][260]
    #pragma unroll
    for (int i = 0; i < 8; i++)
        #pragma unroll
        for (int j = 0; j < 8; j++)
            att[(ty*8 + i)*260 + tx*8 + j] = acc[i][j] * SCALE;
    __syncthreads();
    const int lane = tid & 31, wrp = tid >> 5;
    float* out = g_attn + (size_t)b * Pdim * Pdim;
    #pragma unroll 1
    for (int pass = 0; pass < 8; pass++) {
        int r = pass * 8 + wrp;
        float v[8];
        #pragma unroll
        for (int c = 0; c < 8; c++) v[c] = att[r*260 + lane + 32*c];
        float w[8];
        #pragma unroll
        for (int c = 0; c < 8; c++) w[c] = v[c];
        #pragma unroll
        for (int c = 0; c < 4; c++) w[c] = fmaxf(w[c], w[c+4]);
        w[0] = fmaxf(w[0], w[2]); w[1] = fmaxf(w[1], w[3]);
        float m = fmaxf(w[0], w[1]);
        #pragma unroll
        for (int s = 16; s > 0; s >>= 1)
            m = fmaxf(m, __shfl_down_sync(0xffffffffu, m, s));
        float mx = __shfl_sync(0xffffffffu, m, 0);
        float e[8];
        #pragma unroll
        for (int c = 0; c < 8; c++) e[c] = expf(v[c] - mx);
        float t[8];
        #pragma unroll
        for (int c = 0; c < 8; c++) t[c] = e[c];
        #pragma unroll
        for (int c = 0; c < 4; c++) t[c] += t[c+4];
        t[0] += t[2]; t[1] += t[3];
        float s0 = t[0] + t[1];
        #pragma unroll
        for (int s = 16; s > 0; s >>= 1)
            s0 += __shfl_down_sync(0xffffffffu, s0, s);
        float sum = __shfl_sync(0xffffffffu, s0, 0);
        #pragma unroll
        for (int c = 0; c < 8; c++)
            out[(size_t)(p0 + r) * Pdim + lane + 32*c] = e[c] / sum;
    }
}

// ---------------------------------------------------------------- u = prev + e^{iv} * (attn @ state) (R13 body, occ 4)
__global__ void __launch_bounds__(256, 4) k_av() {
    if (!g_active) return;
    __shared__ float As[16][68];
    __shared__ float Br[16][64], Bi[16][64];
    const int tid = threadIdx.x;
    const int b = blockIdx.z;
    const int p0 = blockIdx.y * 64, n0 = blockIdx.x * 64;
    const int tm = (tid >> 4) * 4, tn = (tid & 15) * 4;
    const int lk = tid & 15, lr = tid >> 4;
    const int ln = tid & 63, lkb = tid >> 6;
    const float* __restrict__ sre = (g_cur ? g_re1 : g_re0) + (size_t)b * Pdim * Ddim;
    const float* __restrict__ sim = (g_cur ? g_im1 : g_im0) + (size_t)b * Pdim * Ddim;
    const float* __restrict__ at  = g_attn + (size_t)b * Pdim * Pdim;
    float ar[4][4] = {}, ai[4][4] = {};
    for (int k0 = 0; k0 < Pdim; k0 += 16) {
        #pragma unroll
        for (int i = 0; i < 4; i++)
            As[lk][lr + 16*i] = at[(size_t)(p0 + lr + 16*i) * Pdim + (k0 + lk)];
        #pragma unroll
        for (int i = 0; i < 4; i++) {
            int kq = k0 + lkb * 4 + i;
            Br[lkb*4 + i][ln] = sre[(size_t)kq * Ddim + n0 + ln];
            Bi[lkb*4 + i][ln] = sim[(size_t)kq * Ddim + n0 + ln];
        }
        __syncthreads();
        #pragma unroll
        for (int kk = 0; kk < 16; kk++) {
            float a[4], br[4], bi[4];
            #pragma unroll
            for (int i = 0; i < 4; i++) {
                a[i]  = As[kk][tm+i];
                br[i] = Br[kk][tn+i];
                bi[i] = Bi[kk][tn+i];
            }
            #pragma unroll
            for (int i = 0; i < 4; i++)
                #pragma unroll
                for (int j = 0; j < 4; j++) {
                    ar[i][j] = fmaf(a[i], br[j], ar[i][j]);
                    ai[i][j] = fmaf(a[i], bi[j], ai[i][j]);
                }
        }
        __syncthreads();
    }
    #pragma unroll
    for (int j = 0; j < 4; j++) {
        int d = n0 + tn + j;
        float cv = g_cv[d], sv = g_sv[d];
        #pragma unroll
        for (int i = 0; i < 4; i++) {
            int p = p0 + tm + i;
            size_t idx = (size_t)b * Pdim * Ddim + (size_t)p * Ddim + d;
            float tr = ar[i][j], ti = ai[i][j];
            g_u_re[idx] = sre[(size_t)p * Ddim + d] + cv * tr - sv * ti;
            g_u_im[idx] = sim[(size_t)p * Ddim + d] + sv * tr + cv * ti;
        }
    }
}

// ---------------------------------------------------------------- new = u @ (ffr + i*ffi) (R13 body, occ 3)
__global__ void __launch_bounds__(256, 3) k_ff(const float* __restrict__ ffr,
                                               const float* __restrict__ ffi) {
    if (!g_active) return;
    __shared__ float Aur[16][68], Aui[16][68];
    __shared__ float Bfr[16][64], Bfi[16][64];
    const int tid = threadIdx.x;
    const int m0 = blockIdx.y * 64, n0 = blockIdx.x * 64;
    const int tm = (tid >> 4) * 4, tn = (tid & 15) * 4;
    const int lk = tid & 15, lr = tid >> 4;
    const int ln = tid & 63, lkb = tid >> 6;
    float* __restrict__ nre = g_cur ? g_re0 : g_re1;
    float* __restrict__ nim = g_cur ? g_im0 : g_im1;
    float cr[4][4] = {}, ci[4][4] = {};
    for (int k0 = 0; k0 < Ddim; k0 += 16) {
        #pragma unroll
        for (int i = 0; i < 4; i++) {
            size_t ga = (size_t)(m0 + lr + 16*i) * Ddim + (k0 + lk);
            Aur[lk][lr + 16*i] = g_u_re[ga];
            Aui[lk][lr + 16*i] = g_u_im[ga];
        }
        #pragma unroll
        for (int i = 0; i < 4; i++) {
            int kd = k0 + lkb * 4 + i;
            Bfr[lkb*4 + i][ln] = ffr[(size_t)kd * Ddim + n0 + ln];
            Bfi[lkb*4 + i][ln] = ffi[(size_t)kd * Ddim + n0 + ln];
        }
        __syncthreads();
        #pragma unroll
        for (int kk = 0; kk < 16; kk++) {
            float ur[4], ui[4], fr[4], fi[4];
            #pragma unroll
            for (int i = 0; i < 4; i++) {
                ur[i] = Aur[kk][tm+i]; ui[i] = Aui[kk][tm+i];
                fr[i] = Bfr[kk][tn+i]; fi[i] = Bfi[kk][tn+i];
            }
            #pragma unroll
            for (int i = 0; i < 4; i++)
                #pragma unroll
                for (int j = 0; j < 4; j++) {
                    cr[i][j] = fmaf(ur[i],  fr[j], cr[i][j]);
                    cr[i][j] = fmaf(-ui[i], fi[j], cr[i][j]);
                    ci[i][j] = fmaf(ur[i],  fi[j], ci[i][j]);
                    ci[i][j] = fmaf(ui[i],  fr[j], ci[i][j]);
                }
        }
        __syncthreads();
    }
    #pragma unroll
    for (int i = 0; i < 4; i++)
        #pragma unroll
        for (int j = 0; j < 4; j++) {
            size_t idx = (size_t)(m0 + tm + i) * Ddim + (n0 + tn + j);
            nre[idx] = cr[i][j];
            nim[idx] = ci[i][j];
        }
}

// ---------------------------------------------------------------- complex_norm (R1 expressions) + fused diff partials
__global__ void k_norm() {
    if (!g_active) return;
    float* nre = g_cur ? g_re0 : g_re1;
    float* nim = g_cur ? g_im0 : g_im1;
    const float* pre = g_cur ? g_re1 : g_re0;
    const float* pim = g_cur ? g_im1 : g_im0;
    const int row = blockIdx.x;
    const int tid = threadIdx.x;
    const size_t base = (size_t)row * Ddim;
    float r0 = nre[base + tid],       i0 = nim[base + tid];
    float r1 = nre[base + tid + 256], i1 = nim[base + tid + 256];
    float m0 = sqrtf(r0*r0 + i0*i0);
    float m1 = sqrtf(r1*r1 + i1*i1);
    __shared__ float s_sum[256], s_sq[256];
    s_sum[tid] = m0 + m1;
    s_sq[tid]  = m0*m0 + m1*m1;
    __syncthreads();
    for (int s = 128; s > 0; s >>= 1) {
        if (tid < s) { s_sum[tid] += s_sum[tid+s]; s_sq[tid] += s_sq[tid+s]; }
        __syncthreads();
    }
    float mean = s_sum[0] * (1.0f / 512.0f);
    float var  = (s_sq[0] - 512.0f * mean * mean) * (1.0f / 511.0f);
    var = fmaxf(var, 0.0f);
    float inv = 1.0f / (sqrtf(var) + 1e-5f);
    float sc0 = tanhf((m0 - mean) * inv) / (m0 + 1e-5f);
    float sc1 = tanhf((m1 - mean) * inv) / (m1 + 1e-5f);
    float nr0 = r0 * sc0, ni0 = i0 * sc0;
    float nr1 = r1 * sc1, ni1 = i1 * sc1;
    nre[base + tid]       = nr0;
    nim[base + tid]       = ni0;
    nre[base + tid + 256] = nr1;
    nim[base + tid + 256] = ni1;
    __shared__ double sd[256], sn[256];
    float pr0 = pre[base + tid],       qi0 = pim[base + tid];
    float pr1 = pre[base + tid + 256], qi1 = pim[base + tid + 256];
    float dr0 = nr0 - pr0, di0 = ni0 - qi0;
    float dr1 = nr1 - pr1, di1 = ni1 - qi1;
    sd[tid] = (double)dr0*dr0 + (double)di0*di0 + (double)dr1*dr1 + (double)di1*di1;
    sn[tid] = (double)nr0*nr0 + (double)ni0*ni0 + (double)nr1*nr1 + (double)ni1*ni1;
    __syncthreads();
    for (int s = 128; s > 0; s >>= 1) {
        if (tid < s) { sd[tid] += sd[tid+s]; sn[tid] += sn[tid+s]; }
        __syncthreads();
    }
    if (tid == 0) { g_part_d[row] = sd[0]; g_part_n[row] = sn[0]; }
}

// ---------------------------------------------------------------- flag: reduce partials, swap buffers
__global__ void k_flag() {
    if (!g_active) return;
    const int tid = threadIdx.x;
    double ld = 0.0, lnn = 0.0;
    for (int i = tid; i < NROWS; i += 1024) { ld += g_part_d[i]; lnn += g_part_n[i]; }
    __shared__ double sd[1024], sn[1024];
    sd[tid] = ld; sn[tid] = lnn;
    __syncthreads();
    for (int s = 512; s > 0; s >>= 1) {
        if (tid < s) { sd[tid] += sd[tid+s]; sn[tid] += sn[tid+s]; }
        __syncthreads();
    }
    if (tid == 0) {
        float diff = (float)(sqrt(sd[0]) / (sqrt(sn[0]) + 1e-8));
        g_cur ^= 1;                          // commit = buffer swap (active known true here)
        if (diff < 1e-3f) g_active = 0;
    }
}

// ---------------------------------------------------------------- mean pool over P
__global__ void k_pool() {
    const float* sre = g_cur ? g_re1 : g_re0;
    const float* sim = g_cur ? g_im1 : g_im0;
    const int idx = blockIdx.x * 256 + threadIdx.x;   // b*D + d
    const int b = idx >> 9, d = idx & (Ddim - 1);
    const size_t base = (size_t)b * Pdim * Ddim + d;
    float accr = 0.0f, acci = 0.0f;
    #pragma unroll 8
    for (int p = 0; p < Pdim; p++) {
        accr += sre[base + (size_t)p * Ddim];
        acci += sim[base + (size_t)p * Ddim];
    }
    g_pool_re[idx] = accr * (1.0f / 256.0f);
    g_pool_im[idx] = acci * (1.0f / 256.0f);
}

// ---------------------------------------------------------------- logits
__global__ void k_logits(float* __restrict__ out, const float* __restrict__ Wr,
                         const float* __restrict__ br, const float* __restrict__ Wi,
                         const float* __restrict__ bi) {
    const int b = blockIdx.x, tid = threadIdx.x;
    float pr0 = g_pool_re[b * Ddim + tid],       pi0 = g_pool_im[b * Ddim + tid];
    float pr1 = g_pool_re[b * Ddim + tid + 256], pi1 = g_pool_im[b * Ddim + tid + 256];
    __shared__ float red[256];
    for (int c = 0; c < Cdim; c++) {
        float v = pr0 * Wr[c * Ddim + tid] + pr1 * Wr[c * Ddim + tid + 256]
                + pi0 * Wi[c * Ddim + tid] + pi1 * Wi[c * Ddim + tid + 256];
        red[tid] = v;
        __syncthreads();
        for (int s = 128; s > 0; s >>= 1) {
            if (tid < s) red[tid] += red[tid+s];
            __syncthreads();
        }
        if (tid == 0) out[b * Cdim + c] = red[0] + br[c] + bi[c];
        __syncthreads();
    }
}

// ---------------------------------------------------------------- launch
extern "C" void kernel_launch(void* const* d_in, const int* in_sizes, int n_in,
                              void* d_out, int out_size) {
    const float* x   = (const float*)d_in[0];
    const float* Wp  = (const float*)d_in[1];
    const float* bp  = (const float*)d_in[2];
    const float* qr  = (const float*)d_in[3];
    const float* kr  = (const float*)d_in[4];
    const float* vr  = (const float*)d_in[5];
    const float* ffr = (const float*)d_in[6];
    const float* ffi = (const float*)d_in[7];
    const float* Wr  = (const float*)d_in[8];
    const float* br  = (const float*)d_in[9];
    const float* Wi  = (const float*)d_in[10];
    const float* bi  = (const float*)d_in[11];
    float* out = (float*)d_out;

    cudaFuncSetAttribute(k_qk, cudaFuncAttributeMaxDynamicSharedMemorySize, QKSM_BYTES);

    k_prep<<<1, 512>>>(qr, kr, vr);
    k_proj<<<dim3(Ddim/64, (Bdim*Pdim)/64), 256>>>(x, Wp, bp);
    for (int step = 0; step < 4; step++) {
        k_qk<<<dim3(Pdim/64, Bdim), 256, QKSM_BYTES>>>();
        k_av<<<dim3(Ddim/64, Pdim/64, Bdim), 256>>>();
        k_ff<<<dim3(Ddim/64, (Bdim*Pdim)/64), 256>>>(ffr, ffi);
        k_norm<<<Bdim*Pdim, 256>>>();
        k_flag<<<1, 1024>>>();
    }
    k_pool<<<(Bdim*Ddim)/256, 256>>>();
    k_logits<<<Bdim, 256>>>(out, Wr, br, Wi, bi);
}